// round 1
// baseline (speedup 1.0000x reference)
#include <cuda_runtime.h>
#include <math.h>

#define NB   128
#define CIN  3
#define DIN  18
#define HIN  34
#define WIN  34
#define COUT 16
#define DOUT 16
#define HOUT 32
#define WOUT 32

// Scratch (device globals: allocation-free per harness rules)
__device__ float g_y[(size_t)NB * COUT * DOUT * HOUT * WOUT];   // 134 MB conv output
__device__ float g_part[NB * COUT * DOUT * 2];                  // per-(b,c,d) partial sum/sumsq

// ---------------------------------------------------------------------------
// Kernel 1: conv3d + bias + channel-mult, write y, per-block stats partials.
// Grid: (DOUT, NB), 256 threads. Thread t: h = t>>3, w0 = (t&7)*4 -> 4 outputs
// per channel, 16 channels.
// ---------------------------------------------------------------------------
__global__ void __launch_bounds__(256) conv_kernel(
    const float* __restrict__ x,
    const float* __restrict__ cw,
    const float* __restrict__ cb,
    const float* __restrict__ mult)
{
    const int d   = blockIdx.x;
    const int b   = blockIdx.y;
    const int tid = threadIdx.x;

    __shared__ float sx[CIN * 3 * HIN * WIN];   // 10404 floats: input slab d..d+2
    __shared__ float sw[COUT * CIN * 27];       // 1296 floats: all weights
    __shared__ float sbm[2 * COUT];             // bias | multiplier
    __shared__ float swarp[8][COUT][2];         // per-warp partial sums

    // Load input slab: x[b][ci][d+kd][:][:]
    const float* xb = x + (size_t)b * (CIN * DIN * HIN * WIN);
    for (int i = tid; i < CIN * 3 * HIN * WIN; i += 256) {
        int ci  = i / (3 * HIN * WIN);
        int r   = i - ci * (3 * HIN * WIN);
        int kd  = r / (HIN * WIN);
        int pos = r - kd * (HIN * WIN);
        sx[i] = xb[ci * (DIN * HIN * WIN) + (d + kd) * (HIN * WIN) + pos];
    }
    for (int i = tid; i < COUT * CIN * 27; i += 256) sw[i] = cw[i];
    if (tid < COUT) { sbm[tid] = cb[tid]; sbm[COUT + tid] = mult[tid]; }
    __syncthreads();

    const int h  = tid >> 3;
    const int w0 = (tid & 7) << 2;

    float acc[COUT][4];
    #pragma unroll
    for (int c = 0; c < COUT; c++)
        #pragma unroll
        for (int j = 0; j < 4; j++) acc[c][j] = 0.0f;

    for (int ci = 0; ci < CIN; ci++) {
        for (int kd = 0; kd < 3; kd++) {
            const float* plane = &sx[(ci * 3 + kd) * (HIN * WIN)];
            const int wbase = (ci * 3 + kd) * 9;
            #pragma unroll
            for (int kh = 0; kh < 3; kh++) {
                const float* p = plane + (h + kh) * WIN + w0;
                float iv[6];
                #pragma unroll
                for (int j = 0; j < 6; j++) iv[j] = p[j];
                #pragma unroll
                for (int kw = 0; kw < 3; kw++) {
                    const float* wp = &sw[wbase + kh * 3 + kw];
                    #pragma unroll
                    for (int c = 0; c < COUT; c++) {
                        const float wt = wp[c * 81];
                        acc[c][0] = fmaf(iv[kw + 0], wt, acc[c][0]);
                        acc[c][1] = fmaf(iv[kw + 1], wt, acc[c][1]);
                        acc[c][2] = fmaf(iv[kw + 2], wt, acc[c][2]);
                        acc[c][3] = fmaf(iv[kw + 3], wt, acc[c][3]);
                    }
                }
            }
        }
    }

    const int lane = tid & 31;
    const int warp = tid >> 5;

    #pragma unroll
    for (int c = 0; c < COUT; c++) {
        const float bias = sbm[c];
        const float mu   = sbm[COUT + c];
        float4 v;
        v.x = (acc[c][0] + bias) * mu;
        v.y = (acc[c][1] + bias) * mu;
        v.z = (acc[c][2] + bias) * mu;
        v.w = (acc[c][3] + bias) * mu;

        *(float4*)&g_y[(((size_t)(b * COUT + c) * DOUT + d) << 10) + h * WOUT + w0] = v;

        float s = v.x + v.y + v.z + v.w;
        float q = v.x * v.x + v.y * v.y + v.z * v.z + v.w * v.w;
        #pragma unroll
        for (int off = 16; off; off >>= 1) {
            s += __shfl_down_sync(0xffffffffu, s, off);
            q += __shfl_down_sync(0xffffffffu, q, off);
        }
        if (lane == 0) { swarp[warp][c][0] = s; swarp[warp][c][1] = q; }
    }
    __syncthreads();

    if (tid < 32) {
        const int c     = tid & 15;
        const int which = tid >> 4;
        float v = 0.0f;
        #pragma unroll
        for (int wi = 0; wi < 8; wi++) v += swarp[wi][c][which];
        g_part[((b * COUT + c) * DOUT + d) * 2 + which] = v;
    }
}

// ---------------------------------------------------------------------------
// Kernel 2: fold partials -> mean/rstd, normalize, clamp, mult, max over c.
// Grid: (DOUT, NB), 256 threads.
// ---------------------------------------------------------------------------
__global__ void __launch_bounds__(256) norm_kernel(
    const float* __restrict__ mult,
    float* __restrict__ out)
{
    const int d   = blockIdx.x;
    const int b   = blockIdx.y;
    const int tid = threadIdx.x;

    __shared__ float smean[COUT], srs[COUT], smu[COUT];

    if (tid < COUT) {
        float s = 0.0f, q = 0.0f;
        #pragma unroll
        for (int dd = 0; dd < DOUT; dd++) {
            s += g_part[((b * COUT + tid) * DOUT + dd) * 2];
            q += g_part[((b * COUT + tid) * DOUT + dd) * 2 + 1];
        }
        const float invN = 1.0f / (float)(DOUT * HOUT * WOUT);
        const float mean = s * invN;
        const float var  = q * invN - mean * mean;
        smean[tid] = mean;
        srs[tid]   = rsqrtf(var + 1e-5f);
        smu[tid]   = mult[tid];
    }
    __syncthreads();

    const int h  = tid >> 3;
    const int w0 = (tid & 7) << 2;

    float m0 = -INFINITY, m1 = -INFINITY, m2 = -INFINITY, m3 = -INFINITY;

    #pragma unroll
    for (int c = 0; c < COUT; c++) {
        const float4 v = *(const float4*)&g_y[
            (((size_t)(b * COUT + c) * DOUT + d) << 10) + h * WOUT + w0];
        const float mean = smean[c];
        const float rs   = srs[c];
        const float mu   = smu[c];
        float r;
        r = fminf(fmaxf((v.x - mean) * rs, -1.0f), 1.0f) * mu; m0 = fmaxf(m0, r);
        r = fminf(fmaxf((v.y - mean) * rs, -1.0f), 1.0f) * mu; m1 = fmaxf(m1, r);
        r = fminf(fmaxf((v.z - mean) * rs, -1.0f), 1.0f) * mu; m2 = fmaxf(m2, r);
        r = fminf(fmaxf((v.w - mean) * rs, -1.0f), 1.0f) * mu; m3 = fmaxf(m3, r);
    }

    *(float4*)&out[(((size_t)b * DOUT + d) << 10) + h * WOUT + w0] =
        make_float4(m0, m1, m2, m3);
}

// ---------------------------------------------------------------------------
extern "C" void kernel_launch(void* const* d_in, const int* in_sizes, int n_in,
                              void* d_out, int out_size)
{
    const float* x    = (const float*)d_in[0];
    const float* cw   = (const float*)d_in[1];
    const float* cb   = (const float*)d_in[2];
    const float* mult = (const float*)d_in[3];
    float* out = (float*)d_out;

    dim3 grid(DOUT, NB);
    conv_kernel<<<grid, 256>>>(x, cw, cb, mult);
    norm_kernel<<<grid, 256>>>(mult, out);
}

// round 2
// speedup vs baseline: 1.0354x; 1.0354x over previous
#include <cuda_runtime.h>
#include <math.h>

#define NB   128
#define CIN  3
#define DIN  18
#define HIN  34
#define WIN  34
#define COUT 16
#define DOUT 16
#define HOUT 32
#define WOUT 32

typedef unsigned long long ull;

// Scratch (device globals: allocation-free per harness rules)
__device__ float g_y[(size_t)NB * COUT * DOUT * HOUT * WOUT];   // 134 MB conv output
__device__ float g_part[NB * COUT * DOUT * 2];                  // per-(b,c,d) partial sum/sumsq

// ---- packed f32x2 helpers (sm_103a FFMA2 path, only reachable via PTX) ----
__device__ __forceinline__ ull ffma2(ull a, ull b, ull c) {
    ull d;
    asm("fma.rn.f32x2 %0, %1, %2, %3;" : "=l"(d) : "l"(a), "l"(b), "l"(c));
    return d;
}
__device__ __forceinline__ ull pack2(float lo, float hi) {
    ull d;
    asm("mov.b64 %0, {%1, %2};" : "=l"(d) : "f"(lo), "f"(hi));
    return d;
}
__device__ __forceinline__ float2 unpack2(ull v) {
    float2 r;
    asm("mov.b64 {%0, %1}, %2;" : "=f"(r.x), "=f"(r.y) : "l"(v));
    return r;
}

// Dynamic smem layout (floats):
//   sx    [10404]  input slab (3 ci x 3 kd x 34 x 34)
//   sw2   [2592]   duplicated weight pairs: [(tap*16 + c)*2 + {0,1}], tap in [0,81)
//   sbm   [32]     bias | multiplier
//   swarp [256]    per-warp partial sums [warp][c][2]
#define SX_F    (CIN * 3 * HIN * WIN)      // 10404
#define SW2_F   (81 * COUT * 2)            // 2592
#define SBM_F   (2 * COUT)                 // 32
#define SWARP_F (8 * COUT * 2)             // 256
#define SMEM_F  (SX_F + SW2_F + SBM_F + SWARP_F)

// ---------------------------------------------------------------------------
// Kernel 1: conv3d + bias + channel-mult via packed FFMA2; write y + partials.
// Grid: (DOUT, NB), 256 threads. Thread t: h = t>>3, w0 = (t&7)*4.
// ---------------------------------------------------------------------------
__global__ void __launch_bounds__(256) conv_kernel(
    const float* __restrict__ x,
    const float* __restrict__ cw,
    const float* __restrict__ cb,
    const float* __restrict__ mult)
{
    extern __shared__ float smem[];
    float* sx    = smem;
    float* sw2   = smem + SX_F;
    float* sbm   = sw2 + SW2_F;
    float* swarp = sbm + SBM_F;

    const int d   = blockIdx.x;
    const int b   = blockIdx.y;
    const int tid = threadIdx.x;

    // Load input slab: x[b][ci][d+kd][:][:]
    const float* xb = x + (size_t)b * (CIN * DIN * HIN * WIN);
    for (int i = tid; i < SX_F; i += 256) {
        int ci  = i / (3 * HIN * WIN);
        int r   = i - ci * (3 * HIN * WIN);
        int kd  = r / (HIN * WIN);
        int pos = r - kd * (HIN * WIN);
        sx[i] = xb[ci * (DIN * HIN * WIN) + (d + kd) * (HIN * WIN) + pos];
    }
    // Duplicated weight pairs: sw2[(tap*16 + c)*2 + {0,1}] = cw[c*81 + tap]
    for (int i = tid; i < 81 * COUT; i += 256) {
        int tap = i >> 4;
        int c   = i & 15;
        float w = cw[c * 81 + tap];
        sw2[i * 2]     = w;
        sw2[i * 2 + 1] = w;
    }
    if (tid < COUT) { sbm[tid] = cb[tid]; sbm[COUT + tid] = mult[tid]; }
    __syncthreads();

    const int h  = tid >> 3;
    const int w0 = (tid & 7) << 2;

    // Packed accumulators: acc2[c][0] = outputs (w0, w0+1), acc2[c][1] = (w0+2, w0+3)
    ull acc2[COUT][2];
    #pragma unroll
    for (int c = 0; c < COUT; c++) { acc2[c][0] = 0ull; acc2[c][1] = 0ull; }

    const ull* wpair = (const ull*)sw2;

    #pragma unroll
    for (int ci = 0; ci < CIN; ci++) {
        #pragma unroll
        for (int kd = 0; kd < 3; kd++) {
            const float* plane = &sx[(ci * 3 + kd) * (HIN * WIN)];
            #pragma unroll
            for (int kh = 0; kh < 3; kh++) {
                const float* p = plane + (h + kh) * WIN + w0;   // 8B aligned
                ull a01 = *(const ull*)(p);
                ull a23 = *(const ull*)(p + 2);
                ull a45 = *(const ull*)(p + 4);
                float2 f01 = unpack2(a01);
                float2 f23 = unpack2(a23);
                float2 f45 = unpack2(a45);
                ull a12 = pack2(f01.y, f23.x);
                ull a34 = pack2(f23.y, f45.x);

                const int base = ((ci * 9 + kd * 3 + kh) * 3) * COUT; // pair idx of kw=0
                #pragma unroll
                for (int c = 0; c < COUT; c++) {
                    ull wk0 = wpair[base + c];
                    ull wk1 = wpair[base + COUT + c];
                    ull wk2 = wpair[base + 2 * COUT + c];
                    acc2[c][0] = ffma2(a01, wk0, acc2[c][0]);
                    acc2[c][1] = ffma2(a23, wk0, acc2[c][1]);
                    acc2[c][0] = ffma2(a12, wk1, acc2[c][0]);
                    acc2[c][1] = ffma2(a34, wk1, acc2[c][1]);
                    acc2[c][0] = ffma2(a23, wk2, acc2[c][0]);
                    acc2[c][1] = ffma2(a45, wk2, acc2[c][1]);
                }
            }
        }
    }

    const int lane = tid & 31;
    const int warp = tid >> 5;

    #pragma unroll
    for (int c = 0; c < COUT; c++) {
        const float bias = sbm[c];
        const float mu   = sbm[COUT + c];
        float2 lo = unpack2(acc2[c][0]);
        float2 hi = unpack2(acc2[c][1]);
        float4 v;
        v.x = (lo.x + bias) * mu;
        v.y = (lo.y + bias) * mu;
        v.z = (hi.x + bias) * mu;
        v.w = (hi.y + bias) * mu;

        *(float4*)&g_y[(((size_t)(b * COUT + c) * DOUT + d) << 10) + h * WOUT + w0] = v;

        float s = v.x + v.y + v.z + v.w;
        float q = v.x * v.x + v.y * v.y + v.z * v.z + v.w * v.w;
        #pragma unroll
        for (int off = 16; off; off >>= 1) {
            s += __shfl_down_sync(0xffffffffu, s, off);
            q += __shfl_down_sync(0xffffffffu, q, off);
        }
        if (lane == 0) {
            swarp[(warp * COUT + c) * 2]     = s;
            swarp[(warp * COUT + c) * 2 + 1] = q;
        }
    }
    __syncthreads();

    if (tid < 32) {
        const int c     = tid & 15;
        const int which = tid >> 4;
        float v = 0.0f;
        #pragma unroll
        for (int wi = 0; wi < 8; wi++) v += swarp[(wi * COUT + c) * 2 + which];
        g_part[((b * COUT + c) * DOUT + d) * 2 + which] = v;
    }
}

// ---------------------------------------------------------------------------
// Kernel 2: fold partials -> mean/rstd, normalize, clamp, mult, max over c.
// Grid: (DOUT, NB), 256 threads.
// ---------------------------------------------------------------------------
__global__ void __launch_bounds__(256) norm_kernel(
    const float* __restrict__ mult,
    float* __restrict__ out)
{
    const int d   = blockIdx.x;
    const int b   = blockIdx.y;
    const int tid = threadIdx.x;

    __shared__ float smean[COUT], srs[COUT], smu[COUT];

    if (tid < COUT) {
        float s = 0.0f, q = 0.0f;
        #pragma unroll
        for (int dd = 0; dd < DOUT; dd++) {
            s += g_part[((b * COUT + tid) * DOUT + dd) * 2];
            q += g_part[((b * COUT + tid) * DOUT + dd) * 2 + 1];
        }
        const float invN = 1.0f / (float)(DOUT * HOUT * WOUT);
        const float mean = s * invN;
        const float var  = q * invN - mean * mean;
        smean[tid] = mean;
        srs[tid]   = rsqrtf(var + 1e-5f);
        smu[tid]   = mult[tid];
    }
    __syncthreads();

    const int h  = tid >> 3;
    const int w0 = (tid & 7) << 2;

    float m0 = -INFINITY, m1 = -INFINITY, m2 = -INFINITY, m3 = -INFINITY;

    #pragma unroll
    for (int c = 0; c < COUT; c++) {
        const float4 v = *(const float4*)&g_y[
            (((size_t)(b * COUT + c) * DOUT + d) << 10) + h * WOUT + w0];
        const float mean = smean[c];
        const float rs   = srs[c];
        const float mu   = smu[c];
        float r;
        r = fminf(fmaxf((v.x - mean) * rs, -1.0f), 1.0f) * mu; m0 = fmaxf(m0, r);
        r = fminf(fmaxf((v.y - mean) * rs, -1.0f), 1.0f) * mu; m1 = fmaxf(m1, r);
        r = fminf(fmaxf((v.z - mean) * rs, -1.0f), 1.0f) * mu; m2 = fmaxf(m2, r);
        r = fminf(fmaxf((v.w - mean) * rs, -1.0f), 1.0f) * mu; m3 = fmaxf(m3, r);
    }

    *(float4*)&out[(((size_t)b * DOUT + d) << 10) + h * WOUT + w0] =
        make_float4(m0, m1, m2, m3);
}

// ---------------------------------------------------------------------------
extern "C" void kernel_launch(void* const* d_in, const int* in_sizes, int n_in,
                              void* d_out, int out_size)
{
    const float* x    = (const float*)d_in[0];
    const float* cw   = (const float*)d_in[1];
    const float* cb   = (const float*)d_in[2];
    const float* mult = (const float*)d_in[3];
    float* out = (float*)d_out;

    const size_t smem_bytes = SMEM_F * sizeof(float);   // ~53 KB
    cudaFuncSetAttribute(conv_kernel,
                         cudaFuncAttributeMaxDynamicSharedMemorySize,
                         (int)smem_bytes);

    dim3 grid(DOUT, NB);
    conv_kernel<<<grid, 256, smem_bytes>>>(x, cw, cb, mult);
    norm_kernel<<<grid, 256>>>(mult, out);
}

// round 4
// speedup vs baseline: 1.3842x; 1.3368x over previous
#include <cuda_runtime.h>
#include <cuda_bf16.h>
#include <math.h>
#include <cstdint>

#define NB   128
#define CIN  3
#define DIN  18
#define HIN  34
#define WIN  34
#define HW   (HIN * WIN)
#define COUT 16
#define DOUT 16
#define HOUT 32
#define WOUT 32

#define KPAD    112          // 27 taps * 4 (kw padded to 4) + 4 extra zero
#define NKS     7            // 112 / 16 k-steps
#define BSTRIDE 120          // B row stride in bf16 (bank-conflict-free)
#define SLAB_F  (9 * 1156 + 16)   // 3ci x 3kd planes of 34x34 + overrun pad

// dynamic smem: [ slab f32 SLAB_F | Bhi bf16 16*BSTRIDE | Blo bf16 16*BSTRIDE ]
#define DSMEM_BYTES (SLAB_F * 4 + 2 * COUT * BSTRIDE * 2)

// Scratch (device globals: allocation-free per harness rules)
__device__ float g_y[(size_t)NB * COUT * DOUT * HOUT * WOUT];   // 134 MB conv output
__device__ float g_part[NB * COUT * DOUT * 2];                  // per-(b,c,d) sum/sumsq

// ---------------- mma.sync m16n8k16 bf16 (classic tensor path) ----------------
__device__ __forceinline__ void mma_bf16(float* c,
                                         uint32_t a0, uint32_t a1, uint32_t a2, uint32_t a3,
                                         uint32_t b0, uint32_t b1) {
    asm volatile(
        "mma.sync.aligned.m16n8k16.row.col.f32.bf16.bf16.f32 "
        "{%0,%1,%2,%3}, {%4,%5,%6,%7}, {%8,%9}, {%0,%1,%2,%3};"
        : "+f"(c[0]), "+f"(c[1]), "+f"(c[2]), "+f"(c[3])
        : "r"(a0), "r"(a1), "r"(a2), "r"(a3), "r"(b0), "r"(b1));
}

// f32 pair -> (hi bf16x2, lo bf16x2); element0 (low 16 bits) = f0
__device__ __forceinline__ void cvt_hilo(float f0, float f1, uint32_t& hi, uint32_t& lo) {
    __nv_bfloat162 h = __floats2bfloat162_rn(f0, f1);
    hi = *reinterpret_cast<uint32_t*>(&h);
    float r0 = f0 - __bfloat162float(h.x);
    float r1 = f1 - __bfloat162float(h.y);
    __nv_bfloat162 l = __floats2bfloat162_rn(r0, r1);
    lo = *reinterpret_cast<uint32_t*>(&l);
}

// ---------------------------------------------------------------------------
// Kernel 1: conv3d + bias + channel-mult via mma.sync bf16 hi/lo implicit GEMM.
// Grid (DOUT, NB), 256 threads = 8 warps. Warp w owns rows t*128 + w*16, all t.
// ---------------------------------------------------------------------------
__global__ void __launch_bounds__(256) conv_kernel(
    const float* __restrict__ x,
    const float* __restrict__ cw,
    const float* __restrict__ cb,
    const float* __restrict__ mult)
{
    extern __shared__ float sm[];
    float*          sx  = sm;
    __nv_bfloat16*  Bhi = (__nv_bfloat16*)(sm + SLAB_F);
    __nv_bfloat16*  Blo = Bhi + COUT * BSTRIDE;

    __shared__ float sbm[2 * COUT];
    __shared__ float sred[8][COUT][2];

    const int tid = threadIdx.x;
    const int wid = tid >> 5;
    const int lid = tid & 31;
    const int d   = blockIdx.x;
    const int b   = blockIdx.y;

    // ---- load input slab: x[b][ci][d+kd][:][:], 9 planes of 34x34 ----
    const float* xb = x + (size_t)b * (CIN * DIN * HW);
    for (int i = tid; i < 9 * 1156; i += 256) {
        const int plane = i / 1156;              // ci*3 + kd
        const int pos   = i - plane * 1156;
        const int ci    = plane / 3;
        const int kd    = plane - ci * 3;
        sx[i] = xb[ci * (DIN * HW) + (d + kd) * HW + pos];
    }
    // ---- build B hi/lo: B[c][k'] ; k' = tap*4 + kw (kw<3 real, else 0) ----
    for (int i = tid; i < COUT * BSTRIDE; i += 256) {
        const int c = i / BSTRIDE;
        const int k = i - c * BSTRIDE;
        float wv = 0.0f;
        if (k < 108 && (k & 3) < 3) wv = cw[c * 81 + (k >> 2) * 3 + (k & 3)];
        __nv_bfloat16 h = __float2bfloat16(wv);
        Bhi[i] = h;
        Blo[i] = __float2bfloat16(wv - __bfloat162float(h));
    }
    if (tid < COUT) { sbm[tid] = cb[tid]; sbm[COUT + tid] = mult[tid]; }
    __syncthreads();

    // ---- per-lane A base offsets (floats) for each (kstep, slot) ----
    const int t4 = lid & 3;
    const int g  = lid >> 2;
    int abase[2 * NKS];
    #pragma unroll
    for (int ks = 0; ks < NKS; ks++) {
        #pragma unroll
        for (int slot = 0; slot < 2; slot++) {
            int k   = ks * 16 + t4 * 2 + slot * 8;
            int tap = k >> 2;
            if (tap > 26) tap = 0;               // pad k-range: B is zero there
            const int plane = tap / 3;
            const int kh    = tap - plane * 3;
            abase[ks * 2 + slot] = plane * 1156 + kh * 34 + (k & 3);
        }
    }

    const int h_lo = wid >> 1;                    // h = t*4 + h_lo
    const int w0   = (wid & 1) * 16 + g;

    // bias/mult for this thread's 4 channels: ch0, ch0+1, ch0+8, ch0+9
    const int ch0 = 2 * t4;
    float bm_b[4] = { sbm[ch0], sbm[ch0 + 1], sbm[ch0 + 8], sbm[ch0 + 9] };
    float bm_m[4] = { sbm[COUT + ch0], sbm[COUT + ch0 + 1],
                      sbm[COUT + ch0 + 8], sbm[COUT + ch0 + 9] };

    float s4[4] = {0.f, 0.f, 0.f, 0.f};
    float q4[4] = {0.f, 0.f, 0.f, 0.f};

    const size_t ybase = ((size_t)b * COUT * DOUT + d) << 10;   // + c*(DOUT<<10) later

    for (int t = 0; t < 8; t++) {
        float acc0[4] = {0.f, 0.f, 0.f, 0.f};
        float acc1[4] = {0.f, 0.f, 0.f, 0.f};

        const int h  = t * 4 + h_lo;
        const int hw = h * 34 + w0;

        #pragma unroll
        for (int ks = 0; ks < NKS; ks++) {
            // A fragments straight from fp32 slab (pairs contiguous in w)
            const float* p0 = sx + abase[ks * 2 + 0] + hw;
            const float* p1 = sx + abase[ks * 2 + 1] + hw;
            uint32_t ah0, al0, ah1, al1, ah2, al2, ah3, al3;
            cvt_hilo(p0[0], p0[1], ah0, al0);     // row g      , k-cols 2t4,2t4+1
            cvt_hilo(p0[8], p0[9], ah1, al1);     // row g+8 (w+8)
            cvt_hilo(p1[0], p1[1], ah2, al2);     // k-cols +8
            cvt_hilo(p1[8], p1[9], ah3, al3);

            // B fragments: n = g (+8 for ntile1), k = ks*16 + 2*t4 (+8 for b1)
            const int bidx = g * BSTRIDE + ks * 16 + t4 * 2;
            const uint32_t bh0 = *(const uint32_t*)(Bhi + bidx);
            const uint32_t bh1 = *(const uint32_t*)(Bhi + bidx + 8);
            const uint32_t bl0 = *(const uint32_t*)(Blo + bidx);
            const uint32_t bl1 = *(const uint32_t*)(Blo + bidx + 8);
            const int bidx2 = bidx + 8 * BSTRIDE;
            const uint32_t Bh0 = *(const uint32_t*)(Bhi + bidx2);
            const uint32_t Bh1 = *(const uint32_t*)(Bhi + bidx2 + 8);
            const uint32_t Bl0 = *(const uint32_t*)(Blo + bidx2);
            const uint32_t Bl1 = *(const uint32_t*)(Blo + bidx2 + 8);

            mma_bf16(acc0, ah0, ah1, ah2, ah3, bh0, bh1);
            mma_bf16(acc0, al0, al1, al2, al3, bh0, bh1);
            mma_bf16(acc0, ah0, ah1, ah2, ah3, bl0, bl1);
            mma_bf16(acc1, ah0, ah1, ah2, ah3, Bh0, Bh1);
            mma_bf16(acc1, al0, al1, al2, al3, Bh0, Bh1);
            mma_bf16(acc1, ah0, ah1, ah2, ah3, Bl0, Bl1);
        }

        // epilogue: bias+mult, store y, accumulate stats
        const int rbase = t * 128 + wid * 16 + g;
        #pragma unroll
        for (int j = 0; j < 4; j++) {
            const int jc = j & 1;                 // channel sub-index
            const int r  = rbase + ((j >> 1) << 3);
            {
                const float v = (acc0[j] + bm_b[jc]) * bm_m[jc];
                const int c = ch0 + jc;
                g_y[ybase + (size_t)c * (DOUT << 10) + r] = v;
                s4[jc] += v; q4[jc] += v * v;
            }
            {
                const float v = (acc1[j] + bm_b[2 + jc]) * bm_m[2 + jc];
                const int c = ch0 + 8 + jc;
                g_y[ybase + (size_t)c * (DOUT << 10) + r] = v;
                s4[2 + jc] += v; q4[2 + jc] += v * v;
            }
        }
    }

    // ---- stats reduction: lanes sharing (lid&3) hold the same channel set ----
    #pragma unroll
    for (int j = 0; j < 4; j++) {
        #pragma unroll
        for (int off = 16; off >= 4; off >>= 1) {
            s4[j] += __shfl_down_sync(0xffffffffu, s4[j], off);
            q4[j] += __shfl_down_sync(0xffffffffu, q4[j], off);
        }
    }
    if (lid < 4) {
        const int c0 = 2 * lid;
        sred[wid][c0][0]     = s4[0];  sred[wid][c0][1]     = q4[0];
        sred[wid][c0 + 1][0] = s4[1];  sred[wid][c0 + 1][1] = q4[1];
        sred[wid][c0 + 8][0] = s4[2];  sred[wid][c0 + 8][1] = q4[2];
        sred[wid][c0 + 9][0] = s4[3];  sred[wid][c0 + 9][1] = q4[3];
    }
    __syncthreads();
    if (tid < 32) {
        const int c = tid & 15, which = tid >> 4;
        float v = 0.f;
        #pragma unroll
        for (int wi = 0; wi < 8; wi++) v += sred[wi][c][which];
        g_part[((b * COUT + c) * DOUT + d) * 2 + which] = v;
    }
}

// ---------------------------------------------------------------------------
// Kernel 2: fold partials -> mean/rstd, normalize, clamp, mult, max over c.
// ---------------------------------------------------------------------------
__global__ void __launch_bounds__(256) norm_kernel(
    const float* __restrict__ mult,
    float* __restrict__ out)
{
    const int d   = blockIdx.x;
    const int b   = blockIdx.y;
    const int tid = threadIdx.x;

    __shared__ float smean[COUT], srs[COUT], smu[COUT];

    if (tid < COUT) {
        float s = 0.0f, q = 0.0f;
        #pragma unroll
        for (int dd = 0; dd < DOUT; dd++) {
            s += g_part[((b * COUT + tid) * DOUT + dd) * 2];
            q += g_part[((b * COUT + tid) * DOUT + dd) * 2 + 1];
        }
        const float invN = 1.0f / (float)(DOUT * HOUT * WOUT);
        const float mean = s * invN;
        const float var  = q * invN - mean * mean;
        smean[tid] = mean;
        srs[tid]   = rsqrtf(var + 1e-5f);
        smu[tid]   = mult[tid];
    }
    __syncthreads();

    const int h  = tid >> 3;
    const int w0 = (tid & 7) << 2;

    float m0 = -INFINITY, m1 = -INFINITY, m2 = -INFINITY, m3 = -INFINITY;

    #pragma unroll
    for (int c = 0; c < COUT; c++) {
        const float4 v = *(const float4*)&g_y[
            (((size_t)(b * COUT + c) * DOUT + d) << 10) + h * WOUT + w0];
        const float mean = smean[c];
        const float rs   = srs[c];
        const float mu   = smu[c];
        float r;
        r = fminf(fmaxf((v.x - mean) * rs, -1.0f), 1.0f) * mu; m0 = fmaxf(m0, r);
        r = fminf(fmaxf((v.y - mean) * rs, -1.0f), 1.0f) * mu; m1 = fmaxf(m1, r);
        r = fminf(fmaxf((v.z - mean) * rs, -1.0f), 1.0f) * mu; m2 = fmaxf(m2, r);
        r = fminf(fmaxf((v.w - mean) * rs, -1.0f), 1.0f) * mu; m3 = fmaxf(m3, r);
    }

    *(float4*)&out[(((size_t)b * DOUT + d) << 10) + h * WOUT + w0] =
        make_float4(m0, m1, m2, m3);
}

// ---------------------------------------------------------------------------
extern "C" void kernel_launch(void* const* d_in, const int* in_sizes, int n_in,
                              void* d_out, int out_size)
{
    const float* x    = (const float*)d_in[0];
    const float* cw   = (const float*)d_in[1];
    const float* cb   = (const float*)d_in[2];
    const float* mult = (const float*)d_in[3];
    float* out = (float*)d_out;

    cudaFuncSetAttribute(conv_kernel,
                         cudaFuncAttributeMaxDynamicSharedMemorySize,
                         DSMEM_BYTES);

    dim3 grid(DOUT, NB);
    conv_kernel<<<grid, 256, DSMEM_BYTES>>>(x, cw, cb, mult);
    norm_kernel<<<grid, 256>>>(mult, out);
}